// round 1
// baseline (speedup 1.0000x reference)
#include <cuda_runtime.h>

#define NN 2048
#define EMBD 16
#define BB 64
#define CC 64

// Scratch (no cudaMalloc allowed): A [N,N], y1 = A@X, y2 = 2A@y1 - X
static __device__ float g_A[NN * NN];
static __device__ float g_y1[BB * NN * CC];
static __device__ float g_y2[BB * NN * CC];

// ---------------------------------------------------------------------------
// K0: A[row,:] = softmax(relu(E[row] . E[j])) over j. One block per row.
// ---------------------------------------------------------------------------
__global__ __launch_bounds__(256) void supports_kernel(const float* __restrict__ E,
                                                       float* __restrict__ A) {
    __shared__ float z[NN];
    __shared__ float red[8];
    __shared__ float en[EMBD];
    int row = blockIdx.x;
    int tid = threadIdx.x;
    if (tid < EMBD) en[tid] = E[row * EMBD + tid];
    __syncthreads();
    float er[EMBD];
#pragma unroll
    for (int d = 0; d < EMBD; d++) er[d] = en[d];

    float lmax = 0.f;  // relu => values >= 0
    for (int j = tid; j < NN; j += 256) {
        const float4* ej = reinterpret_cast<const float4*>(E + (size_t)j * EMBD);
        float s = 0.f;
#pragma unroll
        for (int q = 0; q < 4; q++) {
            float4 v = ej[q];
            s = fmaf(er[q * 4 + 0], v.x, s);
            s = fmaf(er[q * 4 + 1], v.y, s);
            s = fmaf(er[q * 4 + 2], v.z, s);
            s = fmaf(er[q * 4 + 3], v.w, s);
        }
        s = fmaxf(s, 0.f);
        z[j] = s;
        lmax = fmaxf(lmax, s);
    }
#pragma unroll
    for (int o = 16; o > 0; o >>= 1) lmax = fmaxf(lmax, __shfl_xor_sync(~0u, lmax, o));
    if ((tid & 31) == 0) red[tid >> 5] = lmax;
    __syncthreads();
    float bmax = red[0];
#pragma unroll
    for (int w = 1; w < 8; w++) bmax = fmaxf(bmax, red[w]);
    __syncthreads();

    float lsum = 0.f;
    for (int j = tid; j < NN; j += 256) {
        float e = expf(z[j] - bmax);
        z[j] = e;
        lsum += e;
    }
#pragma unroll
    for (int o = 16; o > 0; o >>= 1) lsum += __shfl_xor_sync(~0u, lsum, o);
    if ((tid & 31) == 0) red[tid >> 5] = lsum;
    __syncthreads();
    float bsum = 0.f;
#pragma unroll
    for (int w = 0; w < 8; w++) bsum += red[w];
    float inv = 1.f / bsum;
    for (int j = tid; j < NN; j += 256) A[(size_t)row * NN + j] = z[j] * inv;
}

// ---------------------------------------------------------------------------
// K1/K2: Y[b,n,c] = alpha * sum_m A[n,m]*X[b,m,c]  (+ beta * Z[b,n,c])
// Tile: 128 rows (n) x 64 cols (c, one b per block column) x 16 (m).
// 256 threads, each computes an 8x4 register tile.
// ---------------------------------------------------------------------------
__global__ __launch_bounds__(256) void gemm_kernel(const float* __restrict__ A,
                                                   const float* __restrict__ X,
                                                   const float* __restrict__ Z,
                                                   float* __restrict__ Y,
                                                   float alpha, float beta) {
    __shared__ float As[16][132];  // [k][m-in-tile], padded stride (132*4B % 16B == 0)
    __shared__ float Xs[16][64];   // [k][c]

    int b = blockIdx.y;
    int n0 = blockIdx.x * 128;
    int tid = threadIdx.x;
    int tx = tid & 15;   // c group: c = tx*4 + j
    int ty = tid >> 4;   // n group: n = n0 + ty*8 + i
    const float* Xb = X + (size_t)b * NN * CC;

    float acc[8][4];
#pragma unroll
    for (int i = 0; i < 8; i++)
#pragma unroll
        for (int j = 0; j < 4; j++) acc[i][j] = 0.f;

    int arow = tid >> 2;  // 0..63
    int ac4 = tid & 3;    // 0..3
    int xrow = tid >> 4;  // 0..15
    int xc4 = tid & 15;   // 0..15

    for (int m0 = 0; m0 < NN; m0 += 16) {
        // A tile (128 x 16) -> transposed to As[k][m]
#pragma unroll
        for (int r = 0; r < 2; r++) {
            int rr = arow + r * 64;
            float4 v = *reinterpret_cast<const float4*>(
                A + (size_t)(n0 + rr) * NN + m0 + ac4 * 4);
            As[ac4 * 4 + 0][rr] = v.x;
            As[ac4 * 4 + 1][rr] = v.y;
            As[ac4 * 4 + 2][rr] = v.z;
            As[ac4 * 4 + 3][rr] = v.w;
        }
        // X tile (16 x 64)
        {
            float4 v = *reinterpret_cast<const float4*>(
                Xb + (size_t)(m0 + xrow) * CC + xc4 * 4);
            *reinterpret_cast<float4*>(&Xs[xrow][xc4 * 4]) = v;
        }
        __syncthreads();
#pragma unroll
        for (int k = 0; k < 16; k++) {
            float4 a0 = *reinterpret_cast<const float4*>(&As[k][ty * 8]);
            float4 a1 = *reinterpret_cast<const float4*>(&As[k][ty * 8 + 4]);
            float4 xq = *reinterpret_cast<const float4*>(&Xs[k][tx * 4]);
            float av[8] = {a0.x, a0.y, a0.z, a0.w, a1.x, a1.y, a1.z, a1.w};
            float xv[4] = {xq.x, xq.y, xq.z, xq.w};
#pragma unroll
            for (int i = 0; i < 8; i++)
#pragma unroll
                for (int j = 0; j < 4; j++)
                    acc[i][j] = fmaf(av[i], xv[j], acc[i][j]);
        }
        __syncthreads();
    }

    const float* Zb = Z ? (Z + (size_t)b * NN * CC) : nullptr;
    float* Yb = Y + (size_t)b * NN * CC;
#pragma unroll
    for (int i = 0; i < 8; i++) {
        int n = n0 + ty * 8 + i;
        float4 v;
        v.x = alpha * acc[i][0];
        v.y = alpha * acc[i][1];
        v.z = alpha * acc[i][2];
        v.w = alpha * acc[i][3];
        if (Zb) {
            float4 zv = *reinterpret_cast<const float4*>(Zb + (size_t)n * CC + tx * 4);
            v.x = fmaf(beta, zv.x, v.x);
            v.y = fmaf(beta, zv.y, v.y);
            v.z = fmaf(beta, zv.z, v.z);
            v.w = fmaf(beta, zv.w, v.w);
        }
        *reinterpret_cast<float4*>(Yb + (size_t)n * CC + tx * 4) = v;
    }
}

// ---------------------------------------------------------------------------
// K3: one block per node n.
//   W[n][kk=k*64+i][o] = sum_d E[n,d] * wp[d,k,i,o]  (built in smem, 48KB)
//   bias[n][o]         = sum_d E[n,d] * bp[d,o]
//   out[b,n,o] = bias + sum_kk xg[b][kk] * W[kk][o]
//   xg sources: k=0 -> x, k=1 -> y1, k=2 -> y2; staged in smem [b][196-pad].
// 256 threads as 16(o-groups) x 16(b-groups), 4x4 register tile.
// ---------------------------------------------------------------------------
#define XG_STRIDE 196
__global__ __launch_bounds__(256) void out_kernel(const float* __restrict__ X,
                                                  const float* __restrict__ E,
                                                  const float* __restrict__ wp,
                                                  const float* __restrict__ bp,
                                                  float* __restrict__ OUT) {
    extern __shared__ float sm[];
    float* Ws = sm;                       // 192*64 = 12288
    float* XGs = sm + 12288;              // 64 * XG_STRIDE = 12544
    float* bs = XGs + 64 * XG_STRIDE;     // 64
    __shared__ float en[EMBD];

    int n = blockIdx.x;
    int tid = threadIdx.x;
    if (tid < EMBD) en[tid] = E[n * EMBD + tid];
    __syncthreads();

    // Per-node weights: wp flat layout [d][k*64*64 + i*64 + o] = [d][idx]
    for (int idx = tid; idx < 12288; idx += 256) {
        float s = 0.f;
#pragma unroll
        for (int d = 0; d < EMBD; d++) s = fmaf(en[d], wp[d * 12288 + idx], s);
        Ws[idx] = s;
    }
    if (tid < 64) {
        float s = 0.f;
#pragma unroll
        for (int d = 0; d < EMBD; d++) s = fmaf(en[d], bp[d * 64 + tid], s);
        bs[tid] = s;
    }
    // xg staging: coalesced global reads (consecutive i per b)
    const float* srcs[3] = {X, g_y1, g_y2};
#pragma unroll
    for (int k = 0; k < 3; k++) {
        const float* src = srcs[k];
        for (int idx = tid; idx < BB * CC; idx += 256) {
            int b = idx >> 6;
            int i = idx & 63;
            XGs[b * XG_STRIDE + k * 64 + i] = src[((size_t)b * NN + n) * CC + i];
        }
    }
    __syncthreads();

    int tx = tid & 15;  // o = tx*4 + j
    int ty = tid >> 4;  // b = ty*4 + ii
    float acc[4][4];
#pragma unroll
    for (int ii = 0; ii < 4; ii++)
#pragma unroll
        for (int j = 0; j < 4; j++) acc[ii][j] = 0.f;

#pragma unroll 4
    for (int kk = 0; kk < 192; kk++) {
        float4 w = *reinterpret_cast<const float4*>(&Ws[kk * 64 + tx * 4]);
        float wv[4] = {w.x, w.y, w.z, w.w};
        float av[4];
#pragma unroll
        for (int ii = 0; ii < 4; ii++) av[ii] = XGs[(ty * 4 + ii) * XG_STRIDE + kk];
#pragma unroll
        for (int ii = 0; ii < 4; ii++)
#pragma unroll
            for (int j = 0; j < 4; j++) acc[ii][j] = fmaf(av[ii], wv[j], acc[ii][j]);
    }

#pragma unroll
    for (int ii = 0; ii < 4; ii++) {
        int b = ty * 4 + ii;
        float4 v;
        v.x = acc[ii][0] + bs[tx * 4 + 0];
        v.y = acc[ii][1] + bs[tx * 4 + 1];
        v.z = acc[ii][2] + bs[tx * 4 + 2];
        v.w = acc[ii][3] + bs[tx * 4 + 3];
        *reinterpret_cast<float4*>(OUT + ((size_t)b * NN + n) * CC + tx * 4) = v;
    }
}

// ---------------------------------------------------------------------------
extern "C" void kernel_launch(void* const* d_in, const int* in_sizes, int n_in,
                              void* d_out, int out_size) {
    // Identify inputs robustly by element count (all distinct).
    const float *x = nullptr, *E = nullptr, *wp = nullptr, *bp = nullptr;
    for (int i = 0; i < n_in; i++) {
        switch (in_sizes[i]) {
            case BB * NN * CC:        x = (const float*)d_in[i]; break;   // 8388608
            case NN * EMBD:           E = (const float*)d_in[i]; break;   // 32768
            case EMBD * 3 * CC * CC:  wp = (const float*)d_in[i]; break;  // 196608
            case EMBD * CC:           bp = (const float*)d_in[i]; break;  // 1024
        }
    }
    float* out = (float*)d_out;

    float *A, *y1, *y2;
    cudaGetSymbolAddress((void**)&A, g_A);
    cudaGetSymbolAddress((void**)&y1, g_y1);
    cudaGetSymbolAddress((void**)&y2, g_y2);

    supports_kernel<<<NN, 256>>>(E, A);

    dim3 ggrid(NN / 128, BB);
    gemm_kernel<<<ggrid, 256>>>(A, x, nullptr, y1, 1.f, 0.f);   // y1 = A @ X
    gemm_kernel<<<ggrid, 256>>>(A, y1, x, y2, 2.f, -1.f);       // y2 = 2A@y1 - X

    int smem_bytes = (12288 + 64 * XG_STRIDE + 64) * (int)sizeof(float);
    cudaFuncSetAttribute(out_kernel, cudaFuncAttributeMaxDynamicSharedMemorySize,
                         smem_bytes);
    out_kernel<<<NN, 256, smem_bytes>>>(x, E, wp, bp, out);
}

// round 3
// speedup vs baseline: 2.2818x; 2.2818x over previous
#include <cuda_runtime.h>
#include <cstdint>

#define NN 2048
#define EMBD 16
#define BB 64
#define CC 64

// Scratch (no cudaMalloc allowed)
static __device__ float g_A[NN * NN];           // adjacency (tf32-rounded)
static __device__ float g_XT[BB * CC * NN];     // X^T [b][c][m], tf32-rounded
static __device__ float g_y1[BB * NN * CC];     // A@X (fp32)
static __device__ float g_y1T[BB * CC * NN];    // y1^T [b][c][m], tf32-rounded
static __device__ float g_y2[BB * NN * CC];     // 2A@y1 - X (fp32)
static __device__ float g_W[NN * 3 * CC * CC];  // per-node weights [n][kk][o]

// ---------------------------------------------------------------------------
__device__ __forceinline__ float tf32r(float x) {
    uint32_t o;
    asm("cvt.rna.tf32.f32 %0, %1;" : "=r"(o) : "f"(x));
    return __uint_as_float(o);
}
__device__ __forceinline__ uint32_t smem_u32(const void* p) {
    uint32_t a;
    asm("{ .reg .u64 t; cvta.to.shared.u64 t, %1; cvt.u32.u64 %0, t; }" : "=r"(a) : "l"(p));
    return a;
}
__device__ __forceinline__ void cp16(uint32_t dst, const void* src) {
    asm volatile("cp.async.cg.shared.global [%0], [%1], 16;" :: "r"(dst), "l"(src));
}
__device__ __forceinline__ void cp_commit() { asm volatile("cp.async.commit_group;"); }
__device__ __forceinline__ void cp_wait1() { asm volatile("cp.async.wait_group 1;" ::: "memory"); }
__device__ __forceinline__ void cp_wait0() { asm volatile("cp.async.wait_group 0;" ::: "memory"); }

__device__ __forceinline__ void mma8(float* d, const uint32_t* a, const uint32_t* b) {
    asm volatile(
        "mma.sync.aligned.m16n8k8.row.col.f32.tf32.tf32.f32 "
        "{%0,%1,%2,%3}, {%4,%5,%6,%7}, {%8,%9}, {%0,%1,%2,%3};"
        : "+f"(d[0]), "+f"(d[1]), "+f"(d[2]), "+f"(d[3])
        : "r"(a[0]), "r"(a[1]), "r"(a[2]), "r"(a[3]), "r"(b[0]), "r"(b[1]));
}

// ---------------------------------------------------------------------------
// K0: A[row,:] = tf32_round(softmax(relu(E[row] . E[j])))
// ---------------------------------------------------------------------------
__global__ __launch_bounds__(256) void supports_kernel(const float* __restrict__ E,
                                                       float* __restrict__ A) {
    __shared__ float z[NN];
    __shared__ float red[8];
    __shared__ float en[EMBD];
    int row = blockIdx.x;
    int tid = threadIdx.x;
    if (tid < EMBD) en[tid] = E[row * EMBD + tid];
    __syncthreads();
    float er[EMBD];
#pragma unroll
    for (int d = 0; d < EMBD; d++) er[d] = en[d];

    float lmax = 0.f;
    for (int j = tid; j < NN; j += 256) {
        const float4* ej = reinterpret_cast<const float4*>(E + (size_t)j * EMBD);
        float s = 0.f;
#pragma unroll
        for (int q = 0; q < 4; q++) {
            float4 v = ej[q];
            s = fmaf(er[q * 4 + 0], v.x, s);
            s = fmaf(er[q * 4 + 1], v.y, s);
            s = fmaf(er[q * 4 + 2], v.z, s);
            s = fmaf(er[q * 4 + 3], v.w, s);
        }
        s = fmaxf(s, 0.f);
        z[j] = s;
        lmax = fmaxf(lmax, s);
    }
#pragma unroll
    for (int o = 16; o > 0; o >>= 1) lmax = fmaxf(lmax, __shfl_xor_sync(~0u, lmax, o));
    if ((tid & 31) == 0) red[tid >> 5] = lmax;
    __syncthreads();
    float bmax = red[0];
#pragma unroll
    for (int w = 1; w < 8; w++) bmax = fmaxf(bmax, red[w]);
    __syncthreads();

    float lsum = 0.f;
    for (int j = tid; j < NN; j += 256) {
        float e = expf(z[j] - bmax);
        z[j] = e;
        lsum += e;
    }
#pragma unroll
    for (int o = 16; o > 0; o >>= 1) lsum += __shfl_xor_sync(~0u, lsum, o);
    if ((tid & 31) == 0) red[tid >> 5] = lsum;
    __syncthreads();
    float bsum = 0.f;
#pragma unroll
    for (int w = 0; w < 8; w++) bsum += red[w];
    float inv = 1.f / bsum;
    for (int j = tid; j < NN; j += 256) A[(size_t)row * NN + j] = tf32r(z[j] * inv);
}

// ---------------------------------------------------------------------------
// Transpose per b: dst[b][c][m] = tf32_round(src[b][m][c]). 32x32 tiles.
// ---------------------------------------------------------------------------
__global__ __launch_bounds__(256) void tr_kernel(const float* __restrict__ S,
                                                 float* __restrict__ D) {
    __shared__ float Ts[32][33];
    int m0 = blockIdx.x * 32;
    int c0 = blockIdx.y * 32;
    int b = blockIdx.z;
    int tid = threadIdx.x;
    int r = tid >> 3, q = tid & 7;
    float4 v = *reinterpret_cast<const float4*>(S + ((size_t)b * NN + m0 + r) * CC + c0 + q * 4);
    Ts[r][q * 4 + 0] = v.x;
    Ts[r][q * 4 + 1] = v.y;
    Ts[r][q * 4 + 2] = v.z;
    Ts[r][q * 4 + 3] = v.w;
    __syncthreads();
    float4 o;
    o.x = tf32r(Ts[q * 4 + 0][r]);
    o.y = tf32r(Ts[q * 4 + 1][r]);
    o.z = tf32r(Ts[q * 4 + 2][r]);
    o.w = tf32r(Ts[q * 4 + 3][r]);
    *reinterpret_cast<float4*>(D + ((size_t)b * CC + c0 + r) * NN + m0 + q * 4) = o;
}

// ---------------------------------------------------------------------------
// W precompute: W[n][idx] = sum_d E[n][d] * wp[d][idx]
// ---------------------------------------------------------------------------
__global__ __launch_bounds__(256) void wpre_kernel(const float* __restrict__ E,
                                                   const float* __restrict__ wp,
                                                   float* __restrict__ W) {
    __shared__ float wps[EMBD][256];
    __shared__ float Es[32][EMBD];
    int idx0 = blockIdx.x * 256;
    int n0 = blockIdx.y * 32;
    int tid = threadIdx.x;
#pragma unroll
    for (int i = 0; i < 4; i++) {
        int f = tid + i * 256;
        int d = f >> 6, c4 = f & 63;
        float4 v = *reinterpret_cast<const float4*>(wp + (size_t)d * 12288 + idx0 + c4 * 4);
        *reinterpret_cast<float4*>(&wps[d][c4 * 4]) = v;
    }
    if (tid < 128) {
        int nl = tid >> 2, dq = tid & 3;
        float4 v = *reinterpret_cast<const float4*>(E + (n0 + nl) * EMBD + dq * 4);
        *reinterpret_cast<float4*>(&Es[nl][dq * 4]) = v;
    }
    __syncthreads();
    float wcol[EMBD];
#pragma unroll
    for (int d = 0; d < EMBD; d++) wcol[d] = wps[d][tid];
#pragma unroll 4
    for (int nl = 0; nl < 32; nl++) {
        float s = 0.f;
#pragma unroll
        for (int d = 0; d < EMBD; d++) s = fmaf(Es[nl][d], wcol[d], s);
        W[(size_t)(n0 + nl) * 12288 + idx0 + tid] = s;
    }
}

// ---------------------------------------------------------------------------
// tf32 mma.sync GEMM: D[n, bc] = sum_m A[n,m] * Bt[bc, m]
// CTA 128x128xK32, 8 warps (2x4), warp tile 64x32, double-buffered cp.async.
// mode 1: Y = acc.  mode 2: Y = 2*acc - Xsub.
// Smem rows padded to 36 floats -> conflict-free fragment loads.
// ---------------------------------------------------------------------------
#define SROW 36
#define STAGE_F (128 * SROW)        // floats per operand stage
#define GEMM_SMEM (4 * STAGE_F * 4) // bytes

__global__ __launch_bounds__(256) void mma_gemm(const float* __restrict__ Ag,
                                                const float* __restrict__ Bt,
                                                float* __restrict__ Y,
                                                const float* __restrict__ Xsub,
                                                int mode) {
    extern __shared__ float sm[];
    float* Abuf[2] = {sm, sm + STAGE_F};
    float* Bbuf[2] = {sm + 2 * STAGE_F, sm + 3 * STAGE_F};

    int tid = threadIdx.x;
    int wid = tid >> 5;
    int lid = tid & 31;
    int wm = wid >> 2;  // 0..1 -> m offset *64
    int wn = wid & 3;   // 0..3 -> n offset *32
    int lr = lid >> 2;  // 0..7
    int lc = lid & 3;   // 0..3
    int n0 = blockIdx.x * 128;
    int bc0 = blockIdx.y * 128;

    const float* Arow = Ag + (size_t)n0 * NN;
    const float* Brow = Bt + (size_t)bc0 * NN;

    int ldrow = tid >> 3;  // 0..31
    int ldch = tid & 7;    // 0..7

    auto load_tile = [&](int it, int buf) {
        int m0 = it * 32;
        uint32_t ab = smem_u32(Abuf[buf]);
        uint32_t bb = smem_u32(Bbuf[buf]);
#pragma unroll
        for (int i = 0; i < 4; i++) {
            int row = ldrow + i * 32;
            cp16(ab + (row * SROW + ldch * 4) * 4, Arow + (size_t)row * NN + m0 + ldch * 4);
        }
#pragma unroll
        for (int i = 0; i < 4; i++) {
            int row = ldrow + i * 32;
            cp16(bb + (row * SROW + ldch * 4) * 4, Brow + (size_t)row * NN + m0 + ldch * 4);
        }
        cp_commit();
    };

    float acc[4][4][4];
#pragma unroll
    for (int mt = 0; mt < 4; mt++)
#pragma unroll
        for (int nt = 0; nt < 4; nt++)
#pragma unroll
            for (int q = 0; q < 4; q++) acc[mt][nt][q] = 0.f;

    load_tile(0, 0);
    load_tile(1, 1);

    for (int it = 0; it < NN / 32; it++) {
        int buf = it & 1;
        if (it + 2 < NN / 32) cp_wait1(); else cp_wait0();
        __syncthreads();
        const float* As = Abuf[buf];
        const float* Bs = Bbuf[buf];
#pragma unroll
        for (int ks = 0; ks < 4; ks++) {
            int k0 = ks * 8;
            uint32_t af[4][4];
#pragma unroll
            for (int mt = 0; mt < 4; mt++) {
                int rm = wm * 64 + mt * 16 + lr;
                af[mt][0] = __float_as_uint(As[rm * SROW + k0 + lc]);
                af[mt][1] = __float_as_uint(As[(rm + 8) * SROW + k0 + lc]);
                af[mt][2] = __float_as_uint(As[rm * SROW + k0 + 4 + lc]);
                af[mt][3] = __float_as_uint(As[(rm + 8) * SROW + k0 + 4 + lc]);
            }
            uint32_t bf[4][2];
#pragma unroll
            for (int nt = 0; nt < 4; nt++) {
                int cb = wn * 32 + nt * 8 + lr;
                bf[nt][0] = __float_as_uint(Bs[cb * SROW + k0 + lc]);
                bf[nt][1] = __float_as_uint(Bs[cb * SROW + k0 + 4 + lc]);
            }
#pragma unroll
            for (int mt = 0; mt < 4; mt++)
#pragma unroll
                for (int nt = 0; nt < 4; nt++) mma8(acc[mt][nt], af[mt], bf[nt]);
        }
        __syncthreads();
        if (it + 2 < NN / 32) load_tile(it + 2, buf);
    }

    // Epilogue: lane holds rows (lr, lr+8), cols (2*lc, 2*lc+1) per (mt,nt).
#pragma unroll
    for (int mt = 0; mt < 4; mt++) {
#pragma unroll
        for (int nt = 0; nt < 4; nt++) {
            int n = n0 + wm * 64 + mt * 16 + lr;
            int bc = bc0 + wn * 32 + nt * 8 + lc * 2;
            int b = bc >> 6, c = bc & 63;
            float* y0 = Y + ((size_t)b * NN + n) * CC + c;
            float* y1p = Y + ((size_t)b * NN + n + 8) * CC + c;
            float2 v0 = make_float2(acc[mt][nt][0], acc[mt][nt][1]);
            float2 v1 = make_float2(acc[mt][nt][2], acc[mt][nt][3]);
            if (mode == 2) {
                const float2 x0 = *reinterpret_cast<const float2*>(
                    Xsub + ((size_t)b * NN + n) * CC + c);
                const float2 x1 = *reinterpret_cast<const float2*>(
                    Xsub + ((size_t)b * NN + n + 8) * CC + c);
                v0.x = fmaf(2.f, v0.x, -x0.x);
                v0.y = fmaf(2.f, v0.y, -x0.y);
                v1.x = fmaf(2.f, v1.x, -x1.x);
                v1.y = fmaf(2.f, v1.y, -x1.y);
            }
            *reinterpret_cast<float2*>(y0) = v0;
            *reinterpret_cast<float2*>(y1p) = v1;
        }
    }
}

// ---------------------------------------------------------------------------
// out2: one block per node n; W[n] precomputed in global.
// ---------------------------------------------------------------------------
#define XG_STRIDE 196
__global__ __launch_bounds__(256) void out2_kernel(const float* __restrict__ X,
                                                   const float* __restrict__ E,
                                                   const float* __restrict__ Wg,
                                                   const float* __restrict__ bp,
                                                   float* __restrict__ OUT) {
    extern __shared__ float sm[];
    float* Ws = sm;                    // 12288
    float* XGs = sm + 12288;           // 64 * 196
    float* bs = XGs + 64 * XG_STRIDE;  // 64
    __shared__ float en[EMBD];

    int n = blockIdx.x;
    int tid = threadIdx.x;
    int wid = tid >> 5;
    int lid = tid & 31;
    if (tid < EMBD) en[tid] = E[n * EMBD + tid];
    __syncthreads();

    {
        const float4* src = reinterpret_cast<const float4*>(Wg + (size_t)n * 12288);
        float4* dst = reinterpret_cast<float4*>(Ws);
#pragma unroll
        for (int i = 0; i < 12; i++) dst[tid + i * 256] = src[tid + i * 256];
    }
    if (tid < 64) {
        float s = 0.f;
#pragma unroll
        for (int d = 0; d < EMBD; d++) s = fmaf(en[d], bp[d * 64 + tid], s);
        bs[tid] = s;
    }
    const float* srcs[3] = {X, g_y1, g_y2};
#pragma unroll
    for (int k = 0; k < 3; k++) {
        const float* src = srcs[k];
        for (int idx = tid; idx < BB * CC; idx += 256) {
            int b = idx >> 6;
            int i = idx & 63;
            XGs[b * XG_STRIDE + k * 64 + i] = src[((size_t)b * NN + n) * CC + i];
        }
    }
    __syncthreads();

    float acc[8][2];
#pragma unroll
    for (int i = 0; i < 8; i++) { acc[i][0] = 0.f; acc[i][1] = 0.f; }

    int bbase = wid * 8;
#pragma unroll 2
    for (int kk = 0; kk < 192; kk += 4) {
        float4 av[8];
#pragma unroll
        for (int i = 0; i < 8; i++)
            av[i] = *reinterpret_cast<const float4*>(&XGs[(bbase + i) * XG_STRIDE + kk]);
#pragma unroll
        for (int q = 0; q < 4; q++) {
            float2 wv = *reinterpret_cast<const float2*>(&Ws[(kk + q) * 64 + lid * 2]);
#pragma unroll
            for (int i = 0; i < 8; i++) {
                float a = (q == 0) ? av[i].x : (q == 1) ? av[i].y : (q == 2) ? av[i].z : av[i].w;
                acc[i][0] = fmaf(a, wv.x, acc[i][0]);
                acc[i][1] = fmaf(a, wv.y, acc[i][1]);
            }
        }
    }

    float2 bias = *reinterpret_cast<const float2*>(&bs[lid * 2]);
#pragma unroll
    for (int i = 0; i < 8; i++) {
        int b = bbase + i;
        float2 v;
        v.x = acc[i][0] + bias.x;
        v.y = acc[i][1] + bias.y;
        *reinterpret_cast<float2*>(OUT + ((size_t)b * NN + n) * CC + lid * 2) = v;
    }
}

// ---------------------------------------------------------------------------
extern "C" void kernel_launch(void* const* d_in, const int* in_sizes, int n_in,
                              void* d_out, int out_size) {
    const float *x = nullptr, *E = nullptr, *wp = nullptr, *bp = nullptr;
    for (int i = 0; i < n_in; i++) {
        switch (in_sizes[i]) {
            case BB * NN * CC:       x = (const float*)d_in[i]; break;
            case NN * EMBD:          E = (const float*)d_in[i]; break;
            case EMBD * 3 * CC * CC: wp = (const float*)d_in[i]; break;
            case EMBD * CC:          bp = (const float*)d_in[i]; break;
        }
    }
    float* out = (float*)d_out;

    float *A, *XT, *y1, *y1T, *y2, *W;
    cudaGetSymbolAddress((void**)&A, g_A);
    cudaGetSymbolAddress((void**)&XT, g_XT);
    cudaGetSymbolAddress((void**)&y1, g_y1);
    cudaGetSymbolAddress((void**)&y1T, g_y1T);
    cudaGetSymbolAddress((void**)&y2, g_y2);
    cudaGetSymbolAddress((void**)&W, g_W);

    supports_kernel<<<NN, 256>>>(E, A);
    tr_kernel<<<dim3(NN / 32, CC / 32, BB), 256>>>(x, XT);
    wpre_kernel<<<dim3(48, 64), 256>>>(E, wp, W);

    cudaFuncSetAttribute(mma_gemm, cudaFuncAttributeMaxDynamicSharedMemorySize, GEMM_SMEM);
    dim3 ggrid(NN / 128, (BB * CC) / 128);
    mma_gemm<<<ggrid, 256, GEMM_SMEM>>>(A, XT, y1, nullptr, 1);
    tr_kernel<<<dim3(NN / 32, CC / 32, BB), 256>>>(y1, y1T);
    mma_gemm<<<ggrid, 256, GEMM_SMEM>>>(A, y1T, y2, x, 2);

    int smem_bytes = (12288 + 64 * XG_STRIDE + 64) * (int)sizeof(float);
    cudaFuncSetAttribute(out2_kernel, cudaFuncAttributeMaxDynamicSharedMemorySize, smem_bytes);
    out2_kernel<<<NN, 256, smem_bytes>>>(x, E, W, bp, out);
}

// round 4
// speedup vs baseline: 2.8397x; 1.2445x over previous
#include <cuda_runtime.h>
#include <cstdint>

#define NN 2048
#define EMBD 16
#define BB 64
#define CC 64

// Scratch (no cudaMalloc allowed)
static __device__ float g_A[NN * NN];           // adjacency (tf32-rounded)
static __device__ float g_XT[BB * CC * NN];     // X^T [b][c][m], tf32-rounded
static __device__ float g_y1[BB * NN * CC];     // A@X (fp32)
static __device__ float g_y1T[BB * CC * NN];    // y1^T [b][c][m], tf32-rounded
static __device__ float g_y2[BB * NN * CC];     // 2A@y1 - X (fp32)
static __device__ float g_WT[NN * 3 * CC * CC]; // per-node weights TRANSPOSED [n][o][kk], tf32

// ---------------------------------------------------------------------------
__device__ __forceinline__ float tf32r(float x) {
    uint32_t o;
    asm("cvt.rna.tf32.f32 %0, %1;" : "=r"(o) : "f"(x));
    return __uint_as_float(o);
}
__device__ __forceinline__ uint32_t smem_u32(const void* p) {
    uint32_t a;
    asm("{ .reg .u64 t; cvta.to.shared.u64 t, %1; cvt.u32.u64 %0, t; }" : "=r"(a) : "l"(p));
    return a;
}
__device__ __forceinline__ void cp16(uint32_t dst, const void* src) {
    asm volatile("cp.async.cg.shared.global [%0], [%1], 16;" :: "r"(dst), "l"(src));
}
__device__ __forceinline__ void cp_commit() { asm volatile("cp.async.commit_group;"); }
__device__ __forceinline__ void cp_wait1() { asm volatile("cp.async.wait_group 1;" ::: "memory"); }
__device__ __forceinline__ void cp_wait0() { asm volatile("cp.async.wait_group 0;" ::: "memory"); }

__device__ __forceinline__ void mma8(float* d, const uint32_t* a, const uint32_t* b) {
    asm volatile(
        "mma.sync.aligned.m16n8k8.row.col.f32.tf32.tf32.f32 "
        "{%0,%1,%2,%3}, {%4,%5,%6,%7}, {%8,%9}, {%0,%1,%2,%3};"
        : "+f"(d[0]), "+f"(d[1]), "+f"(d[2]), "+f"(d[3])
        : "r"(a[0]), "r"(a[1]), "r"(a[2]), "r"(a[3]), "r"(b[0]), "r"(b[1]));
}
__device__ __forceinline__ void ldsm4(uint32_t* r, uint32_t addr) {
    asm volatile("ldmatrix.sync.aligned.m8n8.x4.shared.b16 {%0,%1,%2,%3}, [%4];"
                 : "=r"(r[0]), "=r"(r[1]), "=r"(r[2]), "=r"(r[3]) : "r"(addr));
}

// ---------------------------------------------------------------------------
// K0: A[row,:] = tf32_round(softmax(relu(E[row] . E[j])))
// ---------------------------------------------------------------------------
__global__ __launch_bounds__(256) void supports_kernel(const float* __restrict__ E,
                                                       float* __restrict__ A) {
    __shared__ float z[NN];
    __shared__ float red[8];
    __shared__ float en[EMBD];
    int row = blockIdx.x;
    int tid = threadIdx.x;
    if (tid < EMBD) en[tid] = E[row * EMBD + tid];
    __syncthreads();
    float er[EMBD];
#pragma unroll
    for (int d = 0; d < EMBD; d++) er[d] = en[d];

    float lmax = 0.f;
    for (int j = tid; j < NN; j += 256) {
        const float4* ej = reinterpret_cast<const float4*>(E + (size_t)j * EMBD);
        float s = 0.f;
#pragma unroll
        for (int q = 0; q < 4; q++) {
            float4 v = ej[q];
            s = fmaf(er[q * 4 + 0], v.x, s);
            s = fmaf(er[q * 4 + 1], v.y, s);
            s = fmaf(er[q * 4 + 2], v.z, s);
            s = fmaf(er[q * 4 + 3], v.w, s);
        }
        s = fmaxf(s, 0.f);
        z[j] = s;
        lmax = fmaxf(lmax, s);
    }
#pragma unroll
    for (int o = 16; o > 0; o >>= 1) lmax = fmaxf(lmax, __shfl_xor_sync(~0u, lmax, o));
    if ((tid & 31) == 0) red[tid >> 5] = lmax;
    __syncthreads();
    float bmax = red[0];
#pragma unroll
    for (int w = 1; w < 8; w++) bmax = fmaxf(bmax, red[w]);
    __syncthreads();

    float lsum = 0.f;
    for (int j = tid; j < NN; j += 256) {
        float e = expf(z[j] - bmax);
        z[j] = e;
        lsum += e;
    }
#pragma unroll
    for (int o = 16; o > 0; o >>= 1) lsum += __shfl_xor_sync(~0u, lsum, o);
    if ((tid & 31) == 0) red[tid >> 5] = lsum;
    __syncthreads();
    float bsum = 0.f;
#pragma unroll
    for (int w = 0; w < 8; w++) bsum += red[w];
    float inv = 1.f / bsum;
    for (int j = tid; j < NN; j += 256) A[(size_t)row * NN + j] = tf32r(z[j] * inv);
}

// ---------------------------------------------------------------------------
// Transpose per b: dst[b][c][m] = tf32_round(src[b][m][c]). 32x32 tiles.
// ---------------------------------------------------------------------------
__global__ __launch_bounds__(256) void tr_kernel(const float* __restrict__ S,
                                                 float* __restrict__ D) {
    __shared__ float Ts[32][33];
    int m0 = blockIdx.x * 32;
    int c0 = blockIdx.y * 32;
    int b = blockIdx.z;
    int tid = threadIdx.x;
    int r = tid >> 3, q = tid & 7;
    float4 v = *reinterpret_cast<const float4*>(S + ((size_t)b * NN + m0 + r) * CC + c0 + q * 4);
    Ts[r][q * 4 + 0] = v.x;
    Ts[r][q * 4 + 1] = v.y;
    Ts[r][q * 4 + 2] = v.z;
    Ts[r][q * 4 + 3] = v.w;
    __syncthreads();
    float4 o;
    o.x = tf32r(Ts[q * 4 + 0][r]);
    o.y = tf32r(Ts[q * 4 + 1][r]);
    o.z = tf32r(Ts[q * 4 + 2][r]);
    o.w = tf32r(Ts[q * 4 + 3][r]);
    *reinterpret_cast<float4*>(D + ((size_t)b * CC + c0 + r) * NN + m0 + q * 4) = o;
}

// ---------------------------------------------------------------------------
// W precompute (transposed): WT[n][o*192 + kk] = tf32(sum_d E[n,d]*wp[d, kk*64+o])
// grid (48, 64): kk-chunk of 4 (=256 idx) x 32-n chunk. 256 threads.
// thread t: o = t&63, group g = t>>6 handles nl in [g*8, g*8+8).
// ---------------------------------------------------------------------------
__global__ __launch_bounds__(256) void wpre_kernel(const float* __restrict__ E,
                                                   const float* __restrict__ wp,
                                                   float* __restrict__ WT) {
    __shared__ float wps[EMBD][256];
    __shared__ float Es[32][EMBD];
    int k0 = blockIdx.x * 4;            // kk base (4 kk per block)
    int idx0 = blockIdx.x * 256;        // flat wp idx base
    int n0 = blockIdx.y * 32;
    int tid = threadIdx.x;
#pragma unroll
    for (int i = 0; i < 4; i++) {
        int f = tid + i * 256;          // float4 index 0..1023
        int d = f >> 6, c4 = f & 63;
        float4 v = *reinterpret_cast<const float4*>(wp + (size_t)d * 12288 + idx0 + c4 * 4);
        *reinterpret_cast<float4*>(&wps[d][c4 * 4]) = v;
    }
    if (tid < 128) {
        int nl = tid >> 2, dq = tid & 3;
        float4 v = *reinterpret_cast<const float4*>(E + (n0 + nl) * EMBD + dq * 4);
        *reinterpret_cast<float4*>(&Es[nl][dq * 4]) = v;
    }
    __syncthreads();

    int o = tid & 63;
    int g = tid >> 6;
    // cache the 4 kk-columns of wp for this o
    float wc[4][EMBD];
#pragma unroll
    for (int dk = 0; dk < 4; dk++)
#pragma unroll
        for (int d = 0; d < EMBD; d++) wc[dk][d] = wps[d][dk * 64 + o];

#pragma unroll
    for (int q = 0; q < 8; q++) {
        int nl = g * 8 + q;
        float s[4] = {0.f, 0.f, 0.f, 0.f};
#pragma unroll
        for (int d = 0; d < EMBD; d++) {
            float e = Es[nl][d];
#pragma unroll
            for (int dk = 0; dk < 4; dk++) s[dk] = fmaf(e, wc[dk][d], s[dk]);
        }
        float4 v = make_float4(tf32r(s[0]), tf32r(s[1]), tf32r(s[2]), tf32r(s[3]));
        *reinterpret_cast<float4*>(WT + (size_t)(n0 + nl) * 12288 + o * 192 + k0) = v;
    }
}

// ---------------------------------------------------------------------------
// tf32 mma.sync GEMM with ldmatrix + 3-stage cp.async pipeline.
// D[n, bc] = sum_m A[n,m] * Bt[bc, m].  CTA 128x128xK32, 8 warps (2x4).
// mode 1: Y = acc.  mode 2: Y = 2*acc - Xsub.
// ---------------------------------------------------------------------------
#define SROW 36
#define STAGE_F (128 * SROW)            // floats per operand stage (18432 B)
#define GEMM_SMEM (6 * STAGE_F * 4)     // 3 stages x (A,B)

__global__ __launch_bounds__(256) void mma_gemm(const float* __restrict__ Ag,
                                                const float* __restrict__ Bt,
                                                float* __restrict__ Y,
                                                const float* __restrict__ Xsub,
                                                int mode) {
    extern __shared__ float sm[];
    uint32_t sb = smem_u32(sm);
    uint32_t aBuf[3], bBuf[3];
#pragma unroll
    for (int s = 0; s < 3; s++) {
        aBuf[s] = sb + (2 * s) * STAGE_F * 4;
        bBuf[s] = sb + (2 * s + 1) * STAGE_F * 4;
    }

    int tid = threadIdx.x;
    int wid = tid >> 5;
    int lid = tid & 31;
    int wm = wid >> 2;  // 0..1
    int wn = wid & 3;   // 0..3
    int n0 = blockIdx.x * 128;
    int bc0 = blockIdx.y * 128;

    const float* Arow = Ag + (size_t)n0 * NN;
    const float* Brow = Bt + (size_t)bc0 * NN;

    int ldrow = tid >> 3;  // 0..31
    int ldch = tid & 7;    // 0..7

    auto load_tile = [&](int it, int buf) {
        int m0 = it * 32;
#pragma unroll
        for (int i = 0; i < 4; i++) {
            int row = ldrow + i * 32;
            cp16(aBuf[buf] + (row * SROW + ldch * 4) * 4, Arow + (size_t)row * NN + m0 + ldch * 4);
        }
#pragma unroll
        for (int i = 0; i < 4; i++) {
            int row = ldrow + i * 32;
            cp16(bBuf[buf] + (row * SROW + ldch * 4) * 4, Brow + (size_t)row * NN + m0 + ldch * 4);
        }
        cp_commit();
    };

    // ldmatrix lane-relative offsets (bytes)
    int lm = lid >> 3, lrw = lid & 7;
    uint32_t aLaneRel = ((wm * 64 + (lm & 1) * 8 + lrw) * SROW + (lm >> 1) * 4) * 4;
    uint32_t bLaneRel = ((wn * 32 + (lm >> 1) * 8 + lrw) * SROW + (lm & 1) * 4) * 4;

    float acc[4][4][4];
#pragma unroll
    for (int mt = 0; mt < 4; mt++)
#pragma unroll
        for (int nt = 0; nt < 4; nt++)
#pragma unroll
            for (int q = 0; q < 4; q++) acc[mt][nt][q] = 0.f;

    load_tile(0, 0);
    load_tile(1, 1);

    const int ITERS = NN / 32;
    for (int it = 0; it < ITERS; it++) {
        int buf = it % 3;
        if (it == ITERS - 1) cp_wait0(); else cp_wait1();
        __syncthreads();
        uint32_t aB = aBuf[buf] + aLaneRel;
        uint32_t bB = bBuf[buf] + bLaneRel;
#pragma unroll
        for (int ks = 0; ks < 4; ks++) {
            int k0 = ks * 8;
            uint32_t af[4][4];
#pragma unroll
            for (int mt = 0; mt < 4; mt++)
                ldsm4(af[mt], aB + (mt * 16 * SROW + k0) * 4);
            uint32_t bf01[4], bf23[4];
            ldsm4(bf01, bB + k0 * 4);
            ldsm4(bf23, bB + (16 * SROW + k0) * 4);
#pragma unroll
            for (int mt = 0; mt < 4; mt++) {
                mma8(acc[mt][0], af[mt], &bf01[0]);
                mma8(acc[mt][1], af[mt], &bf01[2]);
                mma8(acc[mt][2], af[mt], &bf23[0]);
                mma8(acc[mt][3], af[mt], &bf23[2]);
            }
        }
        if (it + 2 < ITERS) load_tile(it + 2, (it + 2) % 3);
    }

    int lr = lid >> 2, lc = lid & 3;
#pragma unroll
    for (int mt = 0; mt < 4; mt++) {
#pragma unroll
        for (int nt = 0; nt < 4; nt++) {
            int n = n0 + wm * 64 + mt * 16 + lr;
            int bc = bc0 + wn * 32 + nt * 8 + lc * 2;
            int b = bc >> 6, c = bc & 63;
            float2 v0 = make_float2(acc[mt][nt][0], acc[mt][nt][1]);
            float2 v1 = make_float2(acc[mt][nt][2], acc[mt][nt][3]);
            if (mode == 2) {
                const float2 x0 = *reinterpret_cast<const float2*>(
                    Xsub + ((size_t)b * NN + n) * CC + c);
                const float2 x1 = *reinterpret_cast<const float2*>(
                    Xsub + ((size_t)b * NN + n + 8) * CC + c);
                v0.x = fmaf(2.f, v0.x, -x0.x);
                v0.y = fmaf(2.f, v0.y, -x0.y);
                v1.x = fmaf(2.f, v1.x, -x1.x);
                v1.y = fmaf(2.f, v1.y, -x1.y);
            }
            *reinterpret_cast<float2*>(Y + ((size_t)b * NN + n) * CC + c) = v0;
            *reinterpret_cast<float2*>(Y + ((size_t)b * NN + n + 8) * CC + c) = v1;
        }
    }
}

// ---------------------------------------------------------------------------
// out3: per-node tensor-core contraction. One block (128 thr, 4 warps) per n.
//   D[64 b, 64 o] = XG[64 b, 192 kk] @ WT[64 o, 192 kk]^T  + bias
// XG rows staged tf32 in smem (stride 196); WT loaded from global (tf32).
// Warp w: b rows [w*16, w*16+16), all 64 o (8 n-tiles), K loop 24 x k8.
// ---------------------------------------------------------------------------
#define OSTR 196
#define OUT3_SMEM ((64 * OSTR * 2 + 64) * 4)
__global__ __launch_bounds__(128) void out3_kernel(const float* __restrict__ X,
                                                   const float* __restrict__ E,
                                                   const float* __restrict__ WTg,
                                                   const float* __restrict__ bp,
                                                   float* __restrict__ OUT) {
    extern __shared__ float sm[];
    float* XGs = sm;                  // 64 * 196
    float* WTs = sm + 64 * OSTR;      // 64 * 196
    float* bs = sm + 64 * OSTR * 2;   // 64
    __shared__ float en[EMBD];

    int n = blockIdx.x;
    int tid = threadIdx.x;
    int wid = tid >> 5;
    int lid = tid & 31;
    if (tid < EMBD) en[tid] = E[n * EMBD + tid];
    __syncthreads();

    // XG staging (tf32-rounded), 3 sources
    const float* srcs[3] = {X, g_y1, g_y2};
#pragma unroll
    for (int k = 0; k < 3; k++) {
        const float* src = srcs[k];
#pragma unroll
        for (int rep = 0; rep < 32; rep++) {
            int idx = tid + rep * 128;
            int b = idx >> 6, i = idx & 63;
            XGs[b * OSTR + k * 64 + i] = tf32r(src[((size_t)b * NN + n) * CC + i]);
        }
    }
    // WT[n]: 12288 floats, remap stride 192 -> 196
    {
        const float4* src = reinterpret_cast<const float4*>(WTg + (size_t)n * 12288);
#pragma unroll
        for (int rep = 0; rep < 24; rep++) {
            int f4 = tid + rep * 128;       // 0..3071
            int idx = f4 * 4;
            int o = idx / 192, kk = idx - o * 192;
            *reinterpret_cast<float4*>(&WTs[o * OSTR + kk]) = src[f4];
        }
    }
    if (tid < 64) {
        float s = 0.f;
#pragma unroll
        for (int d = 0; d < EMBD; d++) s = fmaf(en[d], bp[d * 64 + tid], s);
        bs[tid] = s;
    }
    __syncthreads();

    int lm = lid >> 3, lrw = lid & 7;
    uint32_t aLane = smem_u32(XGs) + ((wid * 16 + (lm & 1) * 8 + lrw) * OSTR + (lm >> 1) * 4) * 4;
    uint32_t bLane = smem_u32(WTs) + (((lm >> 1) * 8 + lrw) * OSTR + (lm & 1) * 4) * 4;

    float acc[8][4];
#pragma unroll
    for (int nt = 0; nt < 8; nt++)
#pragma unroll
        for (int q = 0; q < 4; q++) acc[nt][q] = 0.f;

#pragma unroll 2
    for (int kt = 0; kt < 24; kt++) {
        int k0 = kt * 8;
        uint32_t af[4];
        ldsm4(af, aLane + k0 * 4);
#pragma unroll
        for (int g = 0; g < 4; g++) {
            uint32_t bf[4];
            ldsm4(bf, bLane + (g * 16 * OSTR + k0) * 4);
            mma8(acc[g * 2 + 0], af, &bf[0]);
            mma8(acc[g * 2 + 1], af, &bf[2]);
        }
    }

    int lr = lid >> 2, lc = lid & 3;
    int b0 = wid * 16 + lr;
#pragma unroll
    for (int nt = 0; nt < 8; nt++) {
        int o = nt * 8 + lc * 2;
        float2 bias = *reinterpret_cast<const float2*>(&bs[o]);
        float2 v0 = make_float2(acc[nt][0] + bias.x, acc[nt][1] + bias.y);
        float2 v1 = make_float2(acc[nt][2] + bias.x, acc[nt][3] + bias.y);
        *reinterpret_cast<float2*>(OUT + ((size_t)b0 * NN + n) * CC + o) = v0;
        *reinterpret_cast<float2*>(OUT + ((size_t)(b0 + 8) * NN + n) * CC + o) = v1;
    }
}

// ---------------------------------------------------------------------------
extern "C" void kernel_launch(void* const* d_in, const int* in_sizes, int n_in,
                              void* d_out, int out_size) {
    const float *x = nullptr, *E = nullptr, *wp = nullptr, *bp = nullptr;
    for (int i = 0; i < n_in; i++) {
        switch (in_sizes[i]) {
            case BB * NN * CC:       x = (const float*)d_in[i]; break;
            case NN * EMBD:          E = (const float*)d_in[i]; break;
            case EMBD * 3 * CC * CC: wp = (const float*)d_in[i]; break;
            case EMBD * CC:          bp = (const float*)d_in[i]; break;
        }
    }
    float* out = (float*)d_out;

    float *A, *XT, *y1, *y1T, *y2, *WT;
    cudaGetSymbolAddress((void**)&A, g_A);
    cudaGetSymbolAddress((void**)&XT, g_XT);
    cudaGetSymbolAddress((void**)&y1, g_y1);
    cudaGetSymbolAddress((void**)&y1T, g_y1T);
    cudaGetSymbolAddress((void**)&y2, g_y2);
    cudaGetSymbolAddress((void**)&WT, g_WT);

    supports_kernel<<<NN, 256>>>(E, A);
    tr_kernel<<<dim3(NN / 32, CC / 32, BB), 256>>>(x, XT);
    wpre_kernel<<<dim3(48, 64), 256>>>(E, wp, WT);

    cudaFuncSetAttribute(mma_gemm, cudaFuncAttributeMaxDynamicSharedMemorySize, GEMM_SMEM);
    dim3 ggrid(NN / 128, (BB * CC) / 128);
    mma_gemm<<<ggrid, 256, GEMM_SMEM>>>(A, XT, y1, nullptr, 1);
    tr_kernel<<<dim3(NN / 32, CC / 32, BB), 256>>>(y1, y1T);
    mma_gemm<<<ggrid, 256, GEMM_SMEM>>>(A, y1T, y2, x, 2);

    cudaFuncSetAttribute(out3_kernel, cudaFuncAttributeMaxDynamicSharedMemorySize, OUT3_SMEM);
    out3_kernel<<<NN, 128, OUT3_SMEM>>>(x, E, WT, bp, out);
}